// round 1
// baseline (speedup 1.0000x reference)
#include <cuda_runtime.h>
#include <math.h>

// Problem dimensions (fixed by setup_inputs)
#define NB 8
#define NS 512
#define NL 4096      // P*G = 64*64
#define NE 768
#define NHD 384
#define NGE 32

// ---------------------------------------------------------------------------
// Static device scratch (no runtime allocation allowed)
// ---------------------------------------------------------------------------
__device__ float g_Q [NB * NS * NE];            // 12.6 MB  (already scaled by HD^-0.5)
__device__ float g_Kf[NB * NL * NE];            // 100.7 MB
__device__ float g_Vf[NB * NL * NE];            // 100.7 MB
__device__ float g_Sc[NB * 2 * NS * NL];        // 134.2 MB (masked scores)
__device__ float g_O [NB * NS * NE];            // 12.6 MB
__device__ unsigned char g_qm[NB * NS];
__device__ unsigned char g_km[NB * NL];
__device__ float g_lam;
__device__ int   g_mode;   // 0 = uint8 masks, 1 = int32, 2 = float32

// ---------------------------------------------------------------------------
// Mask dtype detection: scan first 8192 words of key_mask (safe under every
// candidate storage: uint8 gives exactly 32768 bytes).
//   int32 storage  -> every nonzero word == 1
//   float32 storage-> every nonzero word == 0x3F800000
//   uint8 storage  -> packed 0/1 bytes; almost surely violates both
// ---------------------------------------------------------------------------
__global__ void detect_mode_kernel(const unsigned int* __restrict__ w, int nwords)
{
    __shared__ int bad_i32, bad_f32, any_nz;
    if (threadIdx.x == 0) { bad_i32 = 0; bad_f32 = 0; any_nz = 0; }
    __syncthreads();
    for (int i = threadIdx.x; i < nwords; i += blockDim.x) {
        unsigned int v = w[i];
        if (v != 0u) {
            atomicOr(&any_nz, 1);
            if (v != 1u)           atomicOr(&bad_i32, 1);
            if (v != 0x3F800000u)  atomicOr(&bad_f32, 1);
        }
    }
    __syncthreads();
    if (threadIdx.x == 0) {
        int mode = 0;
        if (any_nz && !bad_i32)      mode = 1;
        else if (any_nz && !bad_f32) mode = 2;
        g_mode = mode;
    }
}

__device__ __forceinline__ unsigned char read_mask(const void* p, int i, int mode)
{
    if (mode == 1) return ((const int*)p)[i] != 0;
    if (mode == 2) return ((const float*)p)[i] != 0.0f;
    return ((const unsigned char*)p)[i] != 0;
}

__global__ void expand_masks_kernel(const void* __restrict__ qmask,
                                    const void* __restrict__ kmask)
{
    int i = blockIdx.x * blockDim.x + threadIdx.x;
    int mode = g_mode;
    if (i < NB * NS) g_qm[i] = read_mask(qmask, i, mode);
    if (i < NB * NL) g_km[i] = read_mask(kmask, i, mode);
}

// ---------------------------------------------------------------------------
// lambda = exp(dot(lq1,lk1)) - exp(dot(lq2,lk2)) + 0.2
// ---------------------------------------------------------------------------
__global__ void lam_kernel(const float* __restrict__ lq1, const float* __restrict__ lk1,
                           const float* __restrict__ lq2, const float* __restrict__ lk2)
{
    __shared__ float r1[256], r2[256];
    int t = threadIdx.x;
    float a = 0.f, b = 0.f;
    for (int i = t; i < NHD; i += 256) { a += lq1[i] * lk1[i]; b += lq2[i] * lk2[i]; }
    r1[t] = a; r2[t] = b; __syncthreads();
    for (int s = 128; s > 0; s >>= 1) {
        if (t < s) { r1[t] += r1[t + s]; r2[t] += r2[t + s]; }
        __syncthreads();
    }
    if (t == 0) g_lam = expf(r1[0]) - expf(r2[0]) + 0.2f;
}

// ---------------------------------------------------------------------------
// Generic NN SGEMM: C[M,N] = alpha * A[M,K] (row-major, lda) * B[K,N] (ldb)
// 128x128 tiles, BK=8, 256 threads, 8x8 register micro-tiles, float4 I/O.
// All dims must be multiples of the tile sizes (true for every call here).
// grid = (N/128, M/128, Z); per-z pointer strides sA/sB/sC.
// ---------------------------------------------------------------------------
__global__ void __launch_bounds__(256) sgemm_nn(
    const float* __restrict__ Ab, const float* __restrict__ Bb, float* __restrict__ Cb,
    int K, int lda, int ldb, int ldc,
    long sA, long sB, long sC, float alpha)
{
    const float* A = Ab + (long)blockIdx.z * sA;
    const float* B = Bb + (long)blockIdx.z * sB;
    float*       C = Cb + (long)blockIdx.z * sC;
    __shared__ float As[8][128];
    __shared__ float Bs[8][128];
    const int bm = blockIdx.y * 128, bn = blockIdx.x * 128;
    const int tid = threadIdx.x;
    const int tx = tid & 15, ty = tid >> 4;
    const int arow = tid >> 1, acol = (tid & 1) << 2;
    const int brow = tid >> 5, bcol = (tid & 31) << 2;

    float acc[8][8];
#pragma unroll
    for (int i = 0; i < 8; i++)
#pragma unroll
        for (int j = 0; j < 8; j++) acc[i][j] = 0.f;

    for (int k0 = 0; k0 < K; k0 += 8) {
        float4 av = *(const float4*)(A + (long)(bm + arow) * lda + (k0 + acol));
        As[acol + 0][arow] = av.x; As[acol + 1][arow] = av.y;
        As[acol + 2][arow] = av.z; As[acol + 3][arow] = av.w;
        *(float4*)&Bs[brow][bcol] =
            *(const float4*)(B + (long)(k0 + brow) * ldb + (bn + bcol));
        __syncthreads();
#pragma unroll
        for (int kk = 0; kk < 8; kk++) {
            float ar[8], br[8];
            *(float4*)(ar)     = *(const float4*)&As[kk][ty * 4];
            *(float4*)(ar + 4) = *(const float4*)&As[kk][64 + ty * 4];
            *(float4*)(br)     = *(const float4*)&Bs[kk][tx * 4];
            *(float4*)(br + 4) = *(const float4*)&Bs[kk][64 + tx * 4];
#pragma unroll
            for (int i = 0; i < 8; i++)
#pragma unroll
                for (int j = 0; j < 8; j++)
                    acc[i][j] += ar[i] * br[j];
        }
        __syncthreads();
    }
#pragma unroll
    for (int i = 0; i < 8; i++) {
        int m = bm + ((i < 4) ? (ty * 4 + i) : (64 + ty * 4 + (i - 4)));
        float* crow = C + (long)m * ldc;
#pragma unroll
        for (int jb = 0; jb < 2; jb++) {
            int n = bn + (jb ? (64 + tx * 4) : (tx * 4));
            float4 v;
            v.x = acc[i][jb * 4 + 0] * alpha; v.y = acc[i][jb * 4 + 1] * alpha;
            v.z = acc[i][jb * 4 + 2] * alpha; v.w = acc[i][jb * 4 + 3] * alpha;
            *(float4*)(crow + n) = v;
        }
    }
}

// ---------------------------------------------------------------------------
// scores[b,h,s,l] = Qh[b,h,s,:] . Kh[b,h,l,:]   (NT GEMM, K=384) with mask:
// !(qm[b,s] && km[b,l]) -> -1e20.  grid = (4096/128, 512/128, 16), z = b*2+h.
// ---------------------------------------------------------------------------
__global__ void __launch_bounds__(256) scores_kernel()
{
    const int z = blockIdx.z;
    const int b = z >> 1, h = z & 1;
    const float* A  = g_Q  + (long)b * NS * NE + h * NHD;   // [NS, NHD] lda=NE
    const float* Bp = g_Kf + (long)b * NL * NE + h * NHD;   // [NL, NHD] ldb=NE
    float*       C  = g_Sc + (long)z * NS * NL;
    const unsigned char* qm = g_qm + b * NS;
    const unsigned char* km = g_km + b * NL;

    __shared__ float As[8][128];
    __shared__ float Bs[8][128];
    const int bm = blockIdx.y * 128, bn = blockIdx.x * 128;
    const int tid = threadIdx.x;
    const int tx = tid & 15, ty = tid >> 4;
    const int arow = tid >> 1, acol = (tid & 1) << 2;

    float acc[8][8];
#pragma unroll
    for (int i = 0; i < 8; i++)
#pragma unroll
        for (int j = 0; j < 8; j++) acc[i][j] = 0.f;

    for (int k0 = 0; k0 < NHD; k0 += 8) {
        float4 av = *(const float4*)(A  + (long)(bm + arow) * NE + (k0 + acol));
        As[acol + 0][arow] = av.x; As[acol + 1][arow] = av.y;
        As[acol + 2][arow] = av.z; As[acol + 3][arow] = av.w;
        float4 bv = *(const float4*)(Bp + (long)(bn + arow) * NE + (k0 + acol));
        Bs[acol + 0][arow] = bv.x; Bs[acol + 1][arow] = bv.y;
        Bs[acol + 2][arow] = bv.z; Bs[acol + 3][arow] = bv.w;
        __syncthreads();
#pragma unroll
        for (int kk = 0; kk < 8; kk++) {
            float ar[8], br[8];
            *(float4*)(ar)     = *(const float4*)&As[kk][ty * 4];
            *(float4*)(ar + 4) = *(const float4*)&As[kk][64 + ty * 4];
            *(float4*)(br)     = *(const float4*)&Bs[kk][tx * 4];
            *(float4*)(br + 4) = *(const float4*)&Bs[kk][64 + tx * 4];
#pragma unroll
            for (int i = 0; i < 8; i++)
#pragma unroll
                for (int j = 0; j < 8; j++)
                    acc[i][j] += ar[i] * br[j];
        }
        __syncthreads();
    }
#pragma unroll
    for (int i = 0; i < 8; i++) {
        int m = bm + ((i < 4) ? (ty * 4 + i) : (64 + ty * 4 + (i - 4)));
        const float qv = qm[m] ? 1.f : 0.f;
        float* crow = C + (long)m * NL;
#pragma unroll
        for (int jb = 0; jb < 2; jb++) {
            int n = bn + (jb ? (64 + tx * 4) : (tx * 4));
            float4 v;
            v.x = (qv != 0.f && km[n + 0]) ? acc[i][jb * 4 + 0] : -1e20f;
            v.y = (qv != 0.f && km[n + 1]) ? acc[i][jb * 4 + 1] : -1e20f;
            v.z = (qv != 0.f && km[n + 2]) ? acc[i][jb * 4 + 2] : -1e20f;
            v.w = (qv != 0.f && km[n + 3]) ? acc[i][jb * 4 + 3] : -1e20f;
            *(float4*)(crow + n) = v;
        }
    }
}

// ---------------------------------------------------------------------------
// Per (b,s) row: dual softmax, dw = a0 - lam*a1, subtract row-min, mask, write.
// One block per row; both 4096-float score rows staged in shared memory.
// ---------------------------------------------------------------------------
__global__ void __launch_bounds__(256) softmax_dw_kernel(float* __restrict__ dw_out)
{
    __shared__ float s0[NL];
    __shared__ float s1[NL];
    __shared__ float red[256];
    const int row = blockIdx.x;              // b*NS + s
    const int b = row >> 9;
    const int t = threadIdx.x;
    const float* r0 = g_Sc + ((long)(b * 2 + 0) * NS + (row & (NS - 1))) * NL;
    const float* r1 = g_Sc + ((long)(b * 2 + 1) * NS + (row & (NS - 1))) * NL;

    float m0 = -3.4e38f, m1 = -3.4e38f;
    for (int i = t * 4; i < NL; i += 1024) {
        float4 v0 = *(const float4*)(r0 + i);
        float4 v1 = *(const float4*)(r1 + i);
        *(float4*)&s0[i] = v0; *(float4*)&s1[i] = v1;
        m0 = fmaxf(m0, fmaxf(fmaxf(v0.x, v0.y), fmaxf(v0.z, v0.w)));
        m1 = fmaxf(m1, fmaxf(fmaxf(v1.x, v1.y), fmaxf(v1.z, v1.w)));
    }
    red[t] = m0; __syncthreads();
    for (int s = 128; s > 0; s >>= 1) { if (t < s) red[t] = fmaxf(red[t], red[t + s]); __syncthreads(); }
    m0 = red[0]; __syncthreads();
    red[t] = m1; __syncthreads();
    for (int s = 128; s > 0; s >>= 1) { if (t < s) red[t] = fmaxf(red[t], red[t + s]); __syncthreads(); }
    m1 = red[0]; __syncthreads();

    float sum0 = 0.f, sum1 = 0.f;
    for (int i = t; i < NL; i += 256) {
        float e0 = expf(s0[i] - m0); s0[i] = e0; sum0 += e0;
        float e1 = expf(s1[i] - m1); s1[i] = e1; sum1 += e1;
    }
    red[t] = sum0; __syncthreads();
    for (int s = 128; s > 0; s >>= 1) { if (t < s) red[t] += red[t + s]; __syncthreads(); }
    sum0 = red[0]; __syncthreads();
    red[t] = sum1; __syncthreads();
    for (int s = 128; s > 0; s >>= 1) { if (t < s) red[t] += red[t + s]; __syncthreads(); }
    sum1 = red[0]; __syncthreads();

    const float inv0 = 1.f / (sum0 + 1e-8f);
    const float inv1 = 1.f / (sum1 + 1e-8f);
    const float lam = g_lam;
    float mn = 3.4e38f;
    for (int i = t; i < NL; i += 256) {
        float d = s0[i] * inv0 - lam * (s1[i] * inv1);
        s0[i] = d;
        mn = fminf(mn, d);
    }
    red[t] = mn; __syncthreads();
    for (int s = 128; s > 0; s >>= 1) { if (t < s) red[t] = fminf(red[t], red[t + s]); __syncthreads(); }
    mn = red[0]; __syncthreads();

    const unsigned char qv = g_qm[row];
    const unsigned char* km = g_km + b * NL;
    float* o = dw_out + (long)row * NL;
    for (int i = t; i < NL; i += 256) {
        float d = s0[i] - mn + 1e-5f;
        if (!qv || !km[i]) d = 0.f;
        o[i] = d;
    }
}

// ---------------------------------------------------------------------------
// RMSNorm (in-place on g_O) * rms_w * (1 - LAMBDA_INIT)
// ---------------------------------------------------------------------------
__global__ void __launch_bounds__(256) rmsnorm_kernel(float* __restrict__ O,
                                                      const float* __restrict__ w)
{
    __shared__ float red[256];
    const int row = blockIdx.x;
    float* o = O + (long)row * NE;
    const int t = threadIdx.x;
    float ss = 0.f;
    for (int i = t; i < NE; i += 256) { float v = o[i]; ss += v * v; }
    red[t] = ss; __syncthreads();
    for (int s = 128; s > 0; s >>= 1) { if (t < s) red[t] += red[t + s]; __syncthreads(); }
    const float sc = (1.0f / sqrtf(red[0] / (float)NE + 1e-5f)) * 0.8f;
    for (int i = t; i < NE; i += 256) o[i] = o[i] * sc * w[i];
}

// ---------------------------------------------------------------------------
// Launch
// ---------------------------------------------------------------------------
extern "C" void kernel_launch(void* const* d_in, const int* in_sizes, int n_in,
                              void* d_out, int out_size)
{
    const float* query = (const float*)d_in[0];   // [B,S,E]
    const float* key   = (const float*)d_in[1];   // [B,P,G,GE] -> [B*L, GE]
    const void*  qmask = d_in[2];                 // [B,S]   bool
    const void*  kmask = d_in[3];                 // [B,P,G] bool
    const float* Wq    = (const float*)d_in[4];   // [E,E]
    const float* Wk    = (const float*)d_in[5];   // [GE,E]
    const float* Wv    = (const float*)d_in[6];   // [GE,E]
    const float* Wout  = (const float*)d_in[7];   // [E,E]
    const float* lq1   = (const float*)d_in[8];
    const float* lk1   = (const float*)d_in[9];
    const float* lq2   = (const float*)d_in[10];
    const float* lk2   = (const float*)d_in[11];
    const float* rms_w = (const float*)d_in[12];

    float* out = (float*)d_out;                      // [B,S,E]
    float* dw  = out + (long)NB * NS * NE;           // [B,S,P,G] flat = [B,S,L]

    void* p;
    float *Qp, *Kp, *Vp, *Op;
    cudaGetSymbolAddress(&p, g_Q);  Qp = (float*)p;
    cudaGetSymbolAddress(&p, g_Kf); Kp = (float*)p;
    cudaGetSymbolAddress(&p, g_Vf); Vp = (float*)p;
    cudaGetSymbolAddress(&p, g_O);  Op = (float*)p;

    // 1) mask dtype detection + expansion; lambda scalar
    detect_mode_kernel<<<1, 256>>>((const unsigned int*)kmask, (NB * NL) / 4);
    expand_masks_kernel<<<(NB * NL + 255) / 256, 256>>>(qmask, kmask);
    lam_kernel<<<1, 256>>>(lq1, lk1, lq2, lk2);

    // 2) projections
    const float qscale = 1.0f / sqrtf((float)NHD);
    sgemm_nn<<<dim3(NE / 128, (NB * NS) / 128, 1), 256>>>(
        query, Wq, Qp, NE, NE, NE, NE, 0, 0, 0, qscale);
    sgemm_nn<<<dim3(NE / 128, (NB * NL) / 128, 1), 256>>>(
        key, Wk, Kp, NGE, NGE, NE, NE, 0, 0, 0, 1.0f);
    sgemm_nn<<<dim3(NE / 128, (NB * NL) / 128, 1), 256>>>(
        key, Wv, Vp, NGE, NGE, NE, NE, 0, 0, 0, 1.0f);

    // 3) masked attention scores (both heads)
    scores_kernel<<<dim3(NL / 128, NS / 128, NB * 2), 256>>>();

    // 4) dual softmax -> differential weights (written straight to d_out)
    softmax_dw_kernel<<<NB * NS, 256>>>(dw);

    // 5) o = dw @ Vf (batched)
    sgemm_nn<<<dim3(NE / 128, NS / 128, NB), 256>>>(
        dw, Vp, Op, NL, NL, NE, NE,
        (long)NS * NL, (long)NL * NE, (long)NS * NE, 1.0f);

    // 6) RMSNorm * rms_w * (1 - lambda_init)
    rmsnorm_kernel<<<NB * NS, 256>>>(Op, rms_w);

    // 7) out = o @ Wout
    sgemm_nn<<<dim3(NE / 128, (NB * NS) / 128, 1), 256>>>(
        Op, Wout, out, NE, NE, NE, NE, 0, 0, 0, 1.0f);
}

// round 2
// speedup vs baseline: 2.5769x; 2.5769x over previous
#include <cuda_runtime.h>
#include <math.h>

// Problem dimensions (fixed by setup_inputs)
#define NB 8
#define NS 512
#define NL 4096      // P*G
#define NE 768
#define NHD 384
#define NGE 32

// ---------------------------------------------------------------------------
// Static device scratch
// ---------------------------------------------------------------------------
__device__ float g_Q [NB * NS * NE];
__device__ float g_Kf[NB * NL * NE];
__device__ float g_Vf[NB * NL * NE];
__device__ float g_Sc[NB * 2 * NS * NL];   // scores; later reused as split-K partials
__device__ float g_O [NB * NS * NE];
__device__ unsigned char g_qm[NB * NS];
__device__ unsigned char g_km[NB * NL];
__device__ float g_lam;
__device__ int   g_mode;

// ---------------------------------------------------------------------------
// Mask dtype detection + expansion (bool storage may be u8/i32/f32)
// ---------------------------------------------------------------------------
__global__ void detect_mode_kernel(const unsigned int* __restrict__ w, int nwords)
{
    __shared__ int bad_i32, bad_f32, any_nz;
    if (threadIdx.x == 0) { bad_i32 = 0; bad_f32 = 0; any_nz = 0; }
    __syncthreads();
    for (int i = threadIdx.x; i < nwords; i += blockDim.x) {
        unsigned int v = w[i];
        if (v != 0u) {
            atomicOr(&any_nz, 1);
            if (v != 1u)           atomicOr(&bad_i32, 1);
            if (v != 0x3F800000u)  atomicOr(&bad_f32, 1);
        }
    }
    __syncthreads();
    if (threadIdx.x == 0) {
        int mode = 0;
        if (any_nz && !bad_i32)      mode = 1;
        else if (any_nz && !bad_f32) mode = 2;
        g_mode = mode;
    }
}

__device__ __forceinline__ unsigned char read_mask(const void* p, int i, int mode)
{
    if (mode == 1) return ((const int*)p)[i] != 0;
    if (mode == 2) return ((const float*)p)[i] != 0.0f;
    return ((const unsigned char*)p)[i] != 0;
}

__global__ void expand_masks_kernel(const void* __restrict__ qmask,
                                    const void* __restrict__ kmask)
{
    int i = blockIdx.x * blockDim.x + threadIdx.x;
    int mode = g_mode;
    if (i < NB * NS) g_qm[i] = read_mask(qmask, i, mode);
    if (i < NB * NL) g_km[i] = read_mask(kmask, i, mode);
}

__global__ void lam_kernel(const float* __restrict__ lq1, const float* __restrict__ lk1,
                           const float* __restrict__ lq2, const float* __restrict__ lk2)
{
    __shared__ float r1[256], r2[256];
    int t = threadIdx.x;
    float a = 0.f, b = 0.f;
    for (int i = t; i < NHD; i += 256) { a += lq1[i] * lk1[i]; b += lq2[i] * lk2[i]; }
    r1[t] = a; r2[t] = b; __syncthreads();
    for (int s = 128; s > 0; s >>= 1) {
        if (t < s) { r1[t] += r1[t + s]; r2[t] += r2[t + s]; }
        __syncthreads();
    }
    if (t == 0) g_lam = expf(r1[0]) - expf(r2[0]) + 0.2f;
}

// ---------------------------------------------------------------------------
// tf32 warp-MMA GEMM core.
//   Block tile 128x128, BK=32, 256 threads (8 warps, warp tile 32x64).
//   A: [M,K] row-major (lda). B: NN -> [K,N] (ldb); NT -> [N,K] (ldb).
//   EPI 0: C = alpha*acc.  EPI 1: scores mask epilogue (-1e20).
//   All dims multiples of tile sizes. Dynamic smem = 71680 B, double-buffered.
// ---------------------------------------------------------------------------
#define SMEM_BYTES ((2*128*36 + 2*32*136) * 4)

__device__ __forceinline__ float tf32r(float x)
{
    unsigned u;
    asm("cvt.rna.tf32.f32 %0, %1;" : "=r"(u) : "f"(x));
    return __uint_as_float(u);
}

__device__ __forceinline__ void mma8(float* d, const unsigned* a, const unsigned* b)
{
    asm volatile(
        "mma.sync.aligned.m16n8k8.row.col.f32.tf32.tf32.f32 "
        "{%0,%1,%2,%3}, {%4,%5,%6,%7}, {%8,%9}, {%0,%1,%2,%3};"
        : "+f"(d[0]), "+f"(d[1]), "+f"(d[2]), "+f"(d[3])
        : "r"(a[0]), "r"(a[1]), "r"(a[2]), "r"(a[3]), "r"(b[0]), "r"(b[1]));
}

template<bool TRANSB, int EPI>
__device__ __forceinline__ void gemm_core(
    const float* __restrict__ A, const float* __restrict__ B, float* __restrict__ C,
    int K, int lda, int ldb, int ldc, float alpha,
    const unsigned char* __restrict__ qm, const unsigned char* __restrict__ km)
{
    extern __shared__ float sm[];
    float* As = sm;               // [2][128][36]
    float* Bs = sm + 2 * 128 * 36; // [2][32][136]
#define AS(bf,r,c) As[(bf)*4608 + (r)*36 + (c)]
#define BS(bf,r,c) Bs[(bf)*4352 + (r)*136 + (c)]

    const int tid  = threadIdx.x;
    const int lane = tid & 31;
    const int wid  = tid >> 5;
    const int wm   = wid & 3;          // 4 warps over M (32 rows each)
    const int wn   = wid >> 2;         // 2 warps over N (64 cols each)
    const int lc   = lane & 3;
    const int lr   = lane >> 2;
    const int bm   = blockIdx.y * 128;
    const int bn   = blockIdx.x * 128;

    float d[2][8][4];
#pragma unroll
    for (int mt = 0; mt < 2; mt++)
#pragma unroll
        for (int nt = 0; nt < 8; nt++)
#pragma unroll
            for (int i = 0; i < 4; i++) d[mt][nt][i] = 0.f;

    float4 ar[4], br[4];
    const int ntile = K >> 5;

    // ---- prologue: tile 0 -> buf 0
    {
        const int k0 = 0;
#pragma unroll
        for (int i = 0; i < 4; i++) {
            int id = tid + i * 256;
            int row = id >> 3, c4 = (id & 7) << 2;
            ar[i] = *(const float4*)(A + (long)(bm + row) * lda + (k0 + c4));
        }
        if (TRANSB) {
#pragma unroll
            for (int i = 0; i < 4; i++) {
                int id = tid + i * 256;
                int n = id >> 3, k4 = (id & 7) << 2;
                br[i] = *(const float4*)(B + (long)(bn + n) * ldb + (k0 + k4));
            }
        } else {
#pragma unroll
            for (int i = 0; i < 4; i++) {
                int id = tid + i * 256;
                int row = id >> 5, c4 = (id & 31) << 2;
                br[i] = *(const float4*)(B + (long)(k0 + row) * ldb + (bn + c4));
            }
        }
#pragma unroll
        for (int i = 0; i < 4; i++) {
            int id = tid + i * 256;
            int row = id >> 3, c4 = (id & 7) << 2;
            float4 cv = make_float4(tf32r(ar[i].x), tf32r(ar[i].y), tf32r(ar[i].z), tf32r(ar[i].w));
            *(float4*)&AS(0, row, c4) = cv;
        }
        if (TRANSB) {
#pragma unroll
            for (int i = 0; i < 4; i++) {
                int id = tid + i * 256;
                int n = id >> 3, k4 = (id & 7) << 2;
                BS(0, k4 + 0, n) = tf32r(br[i].x);
                BS(0, k4 + 1, n) = tf32r(br[i].y);
                BS(0, k4 + 2, n) = tf32r(br[i].z);
                BS(0, k4 + 3, n) = tf32r(br[i].w);
            }
        } else {
#pragma unroll
            for (int i = 0; i < 4; i++) {
                int id = tid + i * 256;
                int row = id >> 5, c4 = (id & 31) << 2;
                float4 cv = make_float4(tf32r(br[i].x), tf32r(br[i].y), tf32r(br[i].z), tf32r(br[i].w));
                *(float4*)&BS(0, row, c4) = cv;
            }
        }
        __syncthreads();
    }

    // ---- main loop
    for (int t = 0; t < ntile; t++) {
        const int cur = t & 1;
        const bool pf = (t + 1 < ntile);
        if (pf) {
            const int k0 = (t + 1) << 5;
#pragma unroll
            for (int i = 0; i < 4; i++) {
                int id = tid + i * 256;
                int row = id >> 3, c4 = (id & 7) << 2;
                ar[i] = *(const float4*)(A + (long)(bm + row) * lda + (k0 + c4));
            }
            if (TRANSB) {
#pragma unroll
                for (int i = 0; i < 4; i++) {
                    int id = tid + i * 256;
                    int n = id >> 3, k4 = (id & 7) << 2;
                    br[i] = *(const float4*)(B + (long)(bn + n) * ldb + (k0 + k4));
                }
            } else {
#pragma unroll
                for (int i = 0; i < 4; i++) {
                    int id = tid + i * 256;
                    int row = id >> 5, c4 = (id & 31) << 2;
                    br[i] = *(const float4*)(B + (long)(k0 + row) * ldb + (bn + c4));
                }
            }
        }

#pragma unroll
        for (int kk = 0; kk < 4; kk++) {
            unsigned afr[2][4], bfr[8][2];
            const int kb = (kk << 3) + lc;
#pragma unroll
            for (int mt = 0; mt < 2; mt++) {
                int r = wm * 32 + mt * 16 + lr;
                afr[mt][0] = __float_as_uint(AS(cur, r,     kb));
                afr[mt][1] = __float_as_uint(AS(cur, r + 8, kb));
                afr[mt][2] = __float_as_uint(AS(cur, r,     kb + 4));
                afr[mt][3] = __float_as_uint(AS(cur, r + 8, kb + 4));
            }
#pragma unroll
            for (int nt = 0; nt < 8; nt++) {
                int n = wn * 64 + nt * 8 + lr;
                bfr[nt][0] = __float_as_uint(BS(cur, kb,     n));
                bfr[nt][1] = __float_as_uint(BS(cur, kb + 4, n));
            }
#pragma unroll
            for (int mt = 0; mt < 2; mt++)
#pragma unroll
                for (int nt = 0; nt < 8; nt++)
                    mma8(d[mt][nt], afr[mt], bfr[nt]);
        }

        if (pf) {
            const int nxt = cur ^ 1;
#pragma unroll
            for (int i = 0; i < 4; i++) {
                int id = tid + i * 256;
                int row = id >> 3, c4 = (id & 7) << 2;
                float4 cv = make_float4(tf32r(ar[i].x), tf32r(ar[i].y), tf32r(ar[i].z), tf32r(ar[i].w));
                *(float4*)&AS(nxt, row, c4) = cv;
            }
            if (TRANSB) {
#pragma unroll
                for (int i = 0; i < 4; i++) {
                    int id = tid + i * 256;
                    int n = id >> 3, k4 = (id & 7) << 2;
                    BS(nxt, k4 + 0, n) = tf32r(br[i].x);
                    BS(nxt, k4 + 1, n) = tf32r(br[i].y);
                    BS(nxt, k4 + 2, n) = tf32r(br[i].z);
                    BS(nxt, k4 + 3, n) = tf32r(br[i].w);
                }
            } else {
#pragma unroll
                for (int i = 0; i < 4; i++) {
                    int id = tid + i * 256;
                    int row = id >> 5, c4 = (id & 31) << 2;
                    float4 cv = make_float4(tf32r(br[i].x), tf32r(br[i].y), tf32r(br[i].z), tf32r(br[i].w));
                    *(float4*)&BS(nxt, row, c4) = cv;
                }
            }
            __syncthreads();
        }
    }

    // ---- epilogue
#pragma unroll
    for (int mt = 0; mt < 2; mt++) {
        const int m0 = bm + wm * 32 + mt * 16 + lr;
        const bool qa = (EPI == 1) ? (qm[m0] != 0)     : true;
        const bool qb = (EPI == 1) ? (qm[m0 + 8] != 0) : true;
#pragma unroll
        for (int nt = 0; nt < 8; nt++) {
            const int n0 = bn + wn * 64 + nt * 8 + lc * 2;
            if (EPI == 0) {
                float2 v01 = make_float2(alpha * d[mt][nt][0], alpha * d[mt][nt][1]);
                float2 v23 = make_float2(alpha * d[mt][nt][2], alpha * d[mt][nt][3]);
                *(float2*)(C + (long)m0 * ldc + n0)       = v01;
                *(float2*)(C + (long)(m0 + 8) * ldc + n0) = v23;
            } else {
                const bool k0m = km[n0] != 0;
                const bool k1m = km[n0 + 1] != 0;
                float2 v01, v23;
                v01.x = (qa && k0m) ? d[mt][nt][0] : -1e20f;
                v01.y = (qa && k1m) ? d[mt][nt][1] : -1e20f;
                v23.x = (qb && k0m) ? d[mt][nt][2] : -1e20f;
                v23.y = (qb && k1m) ? d[mt][nt][3] : -1e20f;
                *(float2*)(C + (long)m0 * ldc + n0)       = v01;
                *(float2*)(C + (long)(m0 + 8) * ldc + n0) = v23;
            }
        }
    }
#undef AS
#undef BS
}

// Thin entry points ---------------------------------------------------------
__global__ void __launch_bounds__(256) k_gemm_nn(
    const float* __restrict__ A, const float* __restrict__ B, float* __restrict__ C,
    int K, int lda, int ldb, int ldc, long sA, long sB, long sC, float alpha)
{
    gemm_core<false, 0>(A + (long)blockIdx.z * sA, B + (long)blockIdx.z * sB,
                        C + (long)blockIdx.z * sC, K, lda, ldb, ldc, alpha,
                        nullptr, nullptr);
}

__global__ void __launch_bounds__(256) k_scores_mma()
{
    const int z = blockIdx.z, b = z >> 1, h = z & 1;
    gemm_core<true, 1>(g_Q + (long)b * NS * NE + h * NHD,
                       g_Kf + (long)b * NL * NE + h * NHD,
                       g_Sc + (long)z * NS * NL,
                       NHD, NE, NE, NL, 1.0f,
                       g_qm + b * NS, g_km + b * NL);
}

__global__ void __launch_bounds__(256) k_dwv(const float* __restrict__ dw,
                                             float* __restrict__ part)
{
    const int z = blockIdx.z, b = z >> 2, c = z & 3;
    gemm_core<false, 0>(dw + (long)b * NS * NL + c * 1024,
                        g_Vf + (long)b * NL * NE + (long)c * 1024 * NE,
                        part + (long)z * NS * NE,
                        1024, NL, NE, NE, 1.0f, nullptr, nullptr);
}

// ---------------------------------------------------------------------------
// Dual softmax -> differential weights
// ---------------------------------------------------------------------------
__global__ void __launch_bounds__(256) softmax_dw_kernel(float* __restrict__ dw_out)
{
    __shared__ float s0[NL];
    __shared__ float s1[NL];
    __shared__ float red[256];
    const int row = blockIdx.x;
    const int b = row >> 9;
    const int t = threadIdx.x;
    const float* r0 = g_Sc + ((long)(b * 2 + 0) * NS + (row & (NS - 1))) * NL;
    const float* r1 = g_Sc + ((long)(b * 2 + 1) * NS + (row & (NS - 1))) * NL;

    float m0 = -3.4e38f, m1 = -3.4e38f;
    for (int i = t * 4; i < NL; i += 1024) {
        float4 v0 = *(const float4*)(r0 + i);
        float4 v1 = *(const float4*)(r1 + i);
        *(float4*)&s0[i] = v0; *(float4*)&s1[i] = v1;
        m0 = fmaxf(m0, fmaxf(fmaxf(v0.x, v0.y), fmaxf(v0.z, v0.w)));
        m1 = fmaxf(m1, fmaxf(fmaxf(v1.x, v1.y), fmaxf(v1.z, v1.w)));
    }
    red[t] = m0; __syncthreads();
    for (int s = 128; s > 0; s >>= 1) { if (t < s) red[t] = fmaxf(red[t], red[t + s]); __syncthreads(); }
    m0 = red[0]; __syncthreads();
    red[t] = m1; __syncthreads();
    for (int s = 128; s > 0; s >>= 1) { if (t < s) red[t] = fmaxf(red[t], red[t + s]); __syncthreads(); }
    m1 = red[0]; __syncthreads();

    float sum0 = 0.f, sum1 = 0.f;
    for (int i = t; i < NL; i += 256) {
        float e0 = expf(s0[i] - m0); s0[i] = e0; sum0 += e0;
        float e1 = expf(s1[i] - m1); s1[i] = e1; sum1 += e1;
    }
    red[t] = sum0; __syncthreads();
    for (int s = 128; s > 0; s >>= 1) { if (t < s) red[t] += red[t + s]; __syncthreads(); }
    sum0 = red[0]; __syncthreads();
    red[t] = sum1; __syncthreads();
    for (int s = 128; s > 0; s >>= 1) { if (t < s) red[t] += red[t + s]; __syncthreads(); }
    sum1 = red[0]; __syncthreads();

    const float inv0 = 1.f / (sum0 + 1e-8f);
    const float inv1 = 1.f / (sum1 + 1e-8f);
    const float lam = g_lam;
    float mn = 3.4e38f;
    for (int i = t; i < NL; i += 256) {
        float v = s0[i] * inv0 - lam * (s1[i] * inv1);
        s0[i] = v;
        mn = fminf(mn, v);
    }
    red[t] = mn; __syncthreads();
    for (int s = 128; s > 0; s >>= 1) { if (t < s) red[t] = fminf(red[t], red[t + s]); __syncthreads(); }
    mn = red[0]; __syncthreads();

    const unsigned char qv = g_qm[row];
    const unsigned char* km = g_km + b * NL;
    float* o = dw_out + (long)row * NL;
    for (int i = t; i < NL; i += 256) {
        float v = s0[i] - mn + 1e-5f;
        if (!qv || !km[i]) v = 0.f;
        o[i] = v;
    }
}

// ---------------------------------------------------------------------------
// Sum 4 split-K partials + RMSNorm * rms_w * (1 - LAMBDA_INIT)
// ---------------------------------------------------------------------------
__global__ void __launch_bounds__(256) rmsnorm4_kernel(const float* __restrict__ part,
                                                       float* __restrict__ O,
                                                       const float* __restrict__ w)
{
    __shared__ float red[256];
    __shared__ float buf[NE];
    const int row = blockIdx.x;           // b*NS + s
    const int b = row >> 9, s = row & (NS - 1);
    const int t = threadIdx.x;
    const long base0 = ((long)(b * 4 + 0) * NS + s) * NE;
    const long base1 = ((long)(b * 4 + 1) * NS + s) * NE;
    const long base2 = ((long)(b * 4 + 2) * NS + s) * NE;
    const long base3 = ((long)(b * 4 + 3) * NS + s) * NE;
    float ss = 0.f;
    for (int i = t; i < NE; i += 256) {
        float v = part[base0 + i] + part[base1 + i] + part[base2 + i] + part[base3 + i];
        buf[i] = v;
        ss += v * v;
    }
    red[t] = ss; __syncthreads();
    for (int st = 128; st > 0; st >>= 1) { if (t < st) red[t] += red[t + st]; __syncthreads(); }
    const float sc = (1.0f / sqrtf(red[0] / (float)NE + 1e-5f)) * 0.8f;
    float* o = O + (long)row * NE;
    for (int i = t; i < NE; i += 256) o[i] = buf[i] * sc * w[i];
}

// ---------------------------------------------------------------------------
// Launch
// ---------------------------------------------------------------------------
extern "C" void kernel_launch(void* const* d_in, const int* in_sizes, int n_in,
                              void* d_out, int out_size)
{
    const float* query = (const float*)d_in[0];
    const float* key   = (const float*)d_in[1];
    const void*  qmask = d_in[2];
    const void*  kmask = d_in[3];
    const float* Wq    = (const float*)d_in[4];
    const float* Wk    = (const float*)d_in[5];
    const float* Wv    = (const float*)d_in[6];
    const float* Wout  = (const float*)d_in[7];
    const float* lq1   = (const float*)d_in[8];
    const float* lk1   = (const float*)d_in[9];
    const float* lq2   = (const float*)d_in[10];
    const float* lk2   = (const float*)d_in[11];
    const float* rms_w = (const float*)d_in[12];

    float* out = (float*)d_out;                      // [B,S,E]
    float* dw  = out + (long)NB * NS * NE;           // [B,S,P,G]

    void* p;
    float *Qp, *Kp, *Vp, *Op, *Scp;
    cudaGetSymbolAddress(&p, g_Q);  Qp  = (float*)p;
    cudaGetSymbolAddress(&p, g_Kf); Kp  = (float*)p;
    cudaGetSymbolAddress(&p, g_Vf); Vp  = (float*)p;
    cudaGetSymbolAddress(&p, g_O);  Op  = (float*)p;
    cudaGetSymbolAddress(&p, g_Sc); Scp = (float*)p;

    cudaFuncSetAttribute(k_gemm_nn,    cudaFuncAttributeMaxDynamicSharedMemorySize, SMEM_BYTES);
    cudaFuncSetAttribute(k_scores_mma, cudaFuncAttributeMaxDynamicSharedMemorySize, SMEM_BYTES);
    cudaFuncSetAttribute(k_dwv,        cudaFuncAttributeMaxDynamicSharedMemorySize, SMEM_BYTES);

    // 1) masks + lambda
    detect_mode_kernel<<<1, 256>>>((const unsigned int*)kmask, (NB * NL) / 4);
    expand_masks_kernel<<<(NB * NL + 255) / 256, 256>>>(qmask, kmask);
    lam_kernel<<<1, 256>>>(lq1, lk1, lq2, lk2);

    // 2) projections (tf32 tensor GEMM)
    const float qscale = 1.0f / sqrtf((float)NHD);
    k_gemm_nn<<<dim3(NE / 128, (NB * NS) / 128, 1), 256, SMEM_BYTES>>>(
        query, Wq, Qp, NE, NE, NE, NE, 0, 0, 0, qscale);
    k_gemm_nn<<<dim3(NE / 128, (NB * NL) / 128, 1), 256, SMEM_BYTES>>>(
        key, Wk, Kp, NGE, NGE, NE, NE, 0, 0, 0, 1.0f);
    k_gemm_nn<<<dim3(NE / 128, (NB * NL) / 128, 1), 256, SMEM_BYTES>>>(
        key, Wv, Vp, NGE, NGE, NE, NE, 0, 0, 0, 1.0f);

    // 3) masked attention scores (NT, fused mask)
    k_scores_mma<<<dim3(NL / 128, NS / 128, NB * 2), 256, SMEM_BYTES>>>();

    // 4) dual softmax -> differential weights (straight into d_out)
    softmax_dw_kernel<<<NB * NS, 256>>>(dw);

    // 5) o = dw @ Vf, split-K=4, partials into g_Sc scratch
    k_dwv<<<dim3(NE / 128, NS / 128, NB * 4), 256, SMEM_BYTES>>>(dw, Scp);

    // 6) reduce partials + RMSNorm
    rmsnorm4_kernel<<<NB * NS, 256>>>(Scp, Op, rms_w);

    // 7) out = o @ Wout
    k_gemm_nn<<<dim3(NE / 128, (NB * NS) / 128, 1), 256, SMEM_BYTES>>>(
        Op, Wout, out, NE, NE, NE, NE, 0, 0, 0, 1.0f);
}